// round 1
// baseline (speedup 1.0000x reference)
#include <cuda_runtime.h>

// CharRNN: 3-layer LSTM, B=256, T=128, H=1024, V=32, fp32.
// Round 1: correctness baseline with fp32 FFMA2 (fma.rn.f32x2) SIMT GEMM.

#define Tn 128
#define Bn 256
#define Hn 1024
#define Vn 32
#define G4 4096   // 4*H

// Scratch (device globals: allocation-guard-safe).
__device__ float g_hs[2][(size_t)Tn * Bn * Hn];  // ping-pong per-layer hidden sequences
__device__ float g_h[Bn * Hn];
__device__ float g_c[Bn * Hn];
__device__ float g_gates[Bn * G4];

typedef unsigned long long u64;

__device__ __forceinline__ u64 ffma2(u64 a, u64 b, u64 c) {
    u64 d;
    asm("fma.rn.f32x2 %0, %1, %2, %3;" : "=l"(d) : "l"(a), "l"(b), "l"(c));
    return d;
}
__device__ __forceinline__ u64 dup2(float x) {
    u64 d;
    asm("mov.b64 %0, {%1, %1};" : "=l"(d) : "f"(x));
    return d;
}

// gates[b, g] = bias[g] (+ W_ihV[g, tok[b,t]] for layer 0)
//              (+ sum_k x[b,k] * W_ih[g,k] for layers 1/2)
//              + sum_k h[b,k] * W_hh[g,k]
// Block tile: 64 (batch) x 128 (gate). grid = (32, 4), block = 256.
__global__ void __launch_bounds__(256, 2) gemm_step_kernel(
    const float* __restrict__ W_ih,    // null for layer 0
    const float* __restrict__ W_hh,
    const float* __restrict__ bias,
    const float* __restrict__ W_ihV,   // [4096, 32] for layer 0, else null
    const int*   __restrict__ tokens,  // [B, T] for layer 0, else null
    int t, int in_sel)
{
    __shared__ float As[16][72];    // [k][m], row padded to 72 (16B-aligned rows)
    __shared__ float Bs[16][132];   // [k][n], row padded to 132

    const int tid = threadIdx.x;
    const int g0 = blockIdx.x * 128;
    const int b0 = blockIdx.y * 64;
    const int ty = tid >> 4;        // 0..15 -> m group (4 rows each)
    const int tx = tid & 15;        // 0..15 -> n lanes (strided pairs)

    u64 acc[4][4];
#pragma unroll
    for (int i = 0; i < 4; i++)
#pragma unroll
        for (int j = 0; j < 4; j++) acc[i][j] = 0ull;

    const int arow = tid >> 2;          // 0..63
    const int akk  = (tid & 3) * 4;     // 0,4,8,12

    for (int phase = 0; phase < 2; phase++) {
        const float* A;
        const float* W;
        if (phase == 0) {
            if (W_ih == nullptr) continue;   // layer 0 has no dense input GEMM
            A = &g_hs[in_sel][(size_t)t * Bn * Hn];
            W = W_ih;
        } else {
            A = g_h;
            W = W_hh;
        }
        for (int k0 = 0; k0 < Hn; k0 += 16) {
            __syncthreads();
            // A tile 64x16, transposed into As[k][m]
            {
                float4 v = *reinterpret_cast<const float4*>(
                    &A[(size_t)(b0 + arow) * Hn + k0 + akk]);
                As[akk + 0][arow] = v.x;
                As[akk + 1][arow] = v.y;
                As[akk + 2][arow] = v.z;
                As[akk + 3][arow] = v.w;
            }
            // W tile 128x16, transposed into Bs[k][n]
#pragma unroll
            for (int r = 0; r < 2; r++) {
                int idx = tid + r * 256;
                int grow = idx >> 2;
                int kk = (idx & 3) * 4;
                float4 v = *reinterpret_cast<const float4*>(
                    &W[(size_t)(g0 + grow) * Hn + k0 + kk]);
                Bs[kk + 0][grow] = v.x;
                Bs[kk + 1][grow] = v.y;
                Bs[kk + 2][grow] = v.z;
                Bs[kk + 3][grow] = v.w;
            }
            __syncthreads();
#pragma unroll
            for (int kt = 0; kt < 16; kt++) {
                float4 av = *reinterpret_cast<const float4*>(&As[kt][ty * 4]);
                u64 a0 = dup2(av.x), a1 = dup2(av.y), a2 = dup2(av.z), a3 = dup2(av.w);
                u64 bv[4];
#pragma unroll
                for (int j = 0; j < 4; j++)
                    bv[j] = *reinterpret_cast<const u64*>(&Bs[kt][j * 32 + tx * 2]);
#pragma unroll
                for (int j = 0; j < 4; j++) {
                    acc[0][j] = ffma2(a0, bv[j], acc[0][j]);
                    acc[1][j] = ffma2(a1, bv[j], acc[1][j]);
                    acc[2][j] = ffma2(a2, bv[j], acc[2][j]);
                    acc[3][j] = ffma2(a3, bv[j], acc[3][j]);
                }
            }
        }
    }

    // Epilogue: add bias (+ one-hot column for layer 0), store gates.
#pragma unroll
    for (int i = 0; i < 4; i++) {
        int b = b0 + ty * 4 + i;
        int tok = (tokens != nullptr) ? tokens[b * Tn + t] : 0;
#pragma unroll
        for (int j = 0; j < 4; j++) {
            int g = g0 + j * 32 + tx * 2;
            float2 r = *reinterpret_cast<float2*>(&acc[i][j]);  // .x -> g, .y -> g+1
            r.x += bias[g];
            r.y += bias[g + 1];
            if (W_ihV != nullptr) {
                r.x += W_ihV[(size_t)g * Vn + tok];
                r.y += W_ihV[(size_t)(g + 1) * Vn + tok];
            }
            *reinterpret_cast<float2*>(&g_gates[(size_t)b * G4 + g]) = r;
        }
    }
}

// LSTM pointwise update + packed-sequence masking. grid = 1024, block = 256.
__global__ void __launch_bounds__(256) update_kernel(
    const int* __restrict__ lengths, int t, int out_sel,
    float* __restrict__ out_h, float* __restrict__ out_c)
{
    int idx = blockIdx.x * 256 + threadIdx.x;   // 0 .. B*H-1
    int b = idx >> 10;
    int j = idx & 1023;
    const float* gr = &g_gates[(size_t)b * G4];
    float gi = gr[j];
    float gf = gr[Hn + j];
    float gg = gr[2 * Hn + j];
    float go = gr[3 * Hn + j];
    float ig = 1.f / (1.f + expf(-gi));
    float fg = 1.f / (1.f + expf(-gf));
    float gt = tanhf(gg);
    float og = 1.f / (1.f + expf(-go));
    float h = g_h[idx];
    float c = g_c[idx];
    if (t < lengths[b]) {
        c = fg * c + ig * gt;
        h = og * tanhf(c);
        g_h[idx] = h;
        g_c[idx] = c;
    }
    g_hs[out_sel][(size_t)t * Bn * Hn + idx] = h;
    if (out_h != nullptr) {
        out_h[idx] = h;
        out_c[idx] = c;
    }
}

__global__ void zero_state_kernel() {
    int idx = blockIdx.x * 256 + threadIdx.x;
    g_h[idx] = 0.f;
    g_c[idx] = 0.f;
}

// logits[b, t, v] = mask * (hs2[t,b,:] . W_out[v,:] + b_out[v]).
// One block per (t, b) row; final layer output lives in g_hs[0].
__global__ void __launch_bounds__(256) head_kernel(
    const float* __restrict__ W_out, const float* __restrict__ b_out,
    const int* __restrict__ lengths, float* __restrict__ out)
{
    __shared__ float row[Hn];
    int r = blockIdx.x;          // r = t*B + b
    int t = r >> 8;
    int b = r & 255;
    int tid = threadIdx.x;
    int lane = tid & 31, w = tid >> 5;
    float* outp = &out[((size_t)b * Tn + t) * Vn];
    if (t >= lengths[b]) {       // uniform per block
        if (tid < Vn) outp[tid] = 0.f;
        return;
    }
    const float* hsrow = &g_hs[0][(size_t)r * Hn];
    *reinterpret_cast<float4*>(&row[tid * 4]) =
        *reinterpret_cast<const float4*>(&hsrow[tid * 4]);
    __syncthreads();
#pragma unroll
    for (int jv = 0; jv < 4; jv++) {
        int v = w * 4 + jv;
        const float* wr = &W_out[(size_t)v * Hn];
        float s = 0.f;
#pragma unroll 8
        for (int k = lane; k < Hn; k += 32) s += row[k] * wr[k];
#pragma unroll
        for (int off = 16; off; off >>= 1) s += __shfl_xor_sync(0xffffffffu, s, off);
        if (lane == 0) outp[v] = s + b_out[v];
    }
}

extern "C" void kernel_launch(void* const* d_in, const int* in_sizes, int n_in,
                              void* d_out, int out_size) {
    const int*   tokens    = (const int*)d_in[0];     // [B, T]
    const int*   lengths   = (const int*)d_in[1];     // [B]
    const float* W_ih0     = (const float*)d_in[2];   // [4096, 32]
    const float* W_hh0     = (const float*)d_in[3];   // [4096, 1024]
    const float* b0        = (const float*)d_in[4];   // [4096]
    const float* W_ih_rest = (const float*)d_in[5];   // [2, 4096, 1024]
    const float* W_hh_rest = (const float*)d_in[6];   // [2, 4096, 1024]
    const float* b_rest    = (const float*)d_in[7];   // [2, 4096]
    const float* W_out     = (const float*)d_in[8];   // [32, 1024]
    const float* b_out     = (const float*)d_in[9];   // [32]
    float* out = (float*)d_out;

    float* out_h_base = out + (size_t)Bn * Tn * Vn;
    float* out_c_base = out_h_base + (size_t)3 * Bn * Hn;

    dim3 ggrid(32, 4);
    for (int layer = 0; layer < 3; layer++) {
        const float* Wih  = (layer == 0) ? nullptr : W_ih_rest + (size_t)(layer - 1) * G4 * Hn;
        const float* Whh  = (layer == 0) ? W_hh0   : W_hh_rest + (size_t)(layer - 1) * G4 * Hn;
        const float* bias = (layer == 0) ? b0      : b_rest    + (size_t)(layer - 1) * G4;
        const float* WihV = (layer == 0) ? W_ih0   : nullptr;
        const int*   toks = (layer == 0) ? tokens  : nullptr;
        // layer0 -> hs[0]; layer1: hs[0] -> hs[1]; layer2: hs[1] -> hs[0]
        int in_sel  = (layer == 1) ? 0 : 1;
        int out_sel = (layer == 1) ? 1 : 0;

        zero_state_kernel<<<1024, 256>>>();
        for (int t = 0; t < Tn; t++) {
            gemm_step_kernel<<<ggrid, 256>>>(Wih, Whh, bias, WihV, toks, t, in_sel);
            bool last = (t == Tn - 1);
            update_kernel<<<1024, 256>>>(
                lengths, t, out_sel,
                last ? out_h_base + (size_t)layer * Bn * Hn : nullptr,
                last ? out_c_base + (size_t)layer * Bn * Hn : nullptr);
        }
    }
    head_kernel<<<Tn * Bn, 256>>>(W_out, b_out, lengths, out);
}

// round 13
// speedup vs baseline: 5.4448x; 5.4448x over previous
#include <cuda_runtime.h>
#include <cuda_bf16.h>
#include <cstdint>

// CharRNN: 3-layer LSTM, B=256, T=128, H=1024, V=32, fp32 I/O.
// Round 13 (resubmit; rounds 11-12 hit GPU-broker acquisition timeouts):
// mma.sync (HMMA) bf16 split-compensated GEMM. tcgen05 is unavailable:
// harness PTX targets compute_103 (no 'a'), which rejects arch-accelerated
// instructions; mma.sync/ldmatrix/cp.async are base-target and compile.

#define Tn 128
#define Bn 256
#define Hn 1024
#define Vn 32
#define G4 4096

// ---------------- device globals (allocation-guard-safe scratch) ----------------
__device__ __nv_bfloat16 g_Whh_hi[3][(size_t)G4 * Hn];
__device__ __nv_bfloat16 g_Whh_lo[3][(size_t)G4 * Hn];
__device__ __nv_bfloat16 g_Wih_hi[2][(size_t)G4 * Hn];
__device__ __nv_bfloat16 g_Wih_lo[2][(size_t)G4 * Hn];
__device__ __nv_bfloat16 g_hsA_hi[2][(size_t)Tn * Bn * Hn];  // layer-output x, split
__device__ __nv_bfloat16 g_hsA_lo[2][(size_t)Tn * Bn * Hn];
__device__ float g_hs_f32[(size_t)Tn * Bn * Hn];             // final layer only (head)
__device__ __nv_bfloat16 g_h_hi[Bn * Hn];
__device__ __nv_bfloat16 g_h_lo[Bn * Hn];
__device__ float g_h_f32[Bn * Hn];
__device__ float g_c_f32[Bn * Hn];
__device__ float g_gates[(size_t)Bn * G4];

// ---------------- helpers ----------------
__device__ __forceinline__ uint32_t smem_u32_of(const void* p) {
    uint32_t a;
    asm("{ .reg .u64 t; cvta.to.shared.u64 t, %1; cvt.u32.u64 %0, t; }" : "=r"(a) : "l"(p));
    return a;
}
#define SWZ128(o) ((o) ^ (((o) >> 3) & 0x70))

#define LDSM4(f_, addr_) \
    asm volatile("ldmatrix.sync.aligned.m8n8.x4.shared.b16 {%0,%1,%2,%3}, [%4];" \
        : "=r"((f_)[0]), "=r"((f_)[1]), "=r"((f_)[2]), "=r"((f_)[3]) : "r"(addr_))

#define MMA16816(c_, a_, b0_, b1_) \
    asm volatile("mma.sync.aligned.m16n8k16.row.col.f32.bf16.bf16.f32 " \
        "{%0,%1,%2,%3}, {%4,%5,%6,%7}, {%8,%9}, {%0,%1,%2,%3};" \
        : "+f"((c_)[0]), "+f"((c_)[1]), "+f"((c_)[2]), "+f"((c_)[3]) \
        : "r"((a_)[0]), "r"((a_)[1]), "r"((a_)[2]), "r"((a_)[3]), \
          "r"(b0_), "r"(b1_))

// ---------------- weight prep: fp32 -> bf16 hi/lo split ----------------
__global__ void prep_weights_kernel(const float* __restrict__ W_hh0,
                                    const float* __restrict__ W_ih_rest,
                                    const float* __restrict__ W_hh_rest) {
    size_t i = (size_t)blockIdx.x * 256 + threadIdx.x;
    const size_t MS = (size_t)G4 * Hn;
    if (i >= 5 * MS) return;
    int m = (int)(i / MS);
    size_t r = i % MS;
    float x;
    __nv_bfloat16 *dh, *dl;
    if (m == 0)      { x = W_hh0[r];           dh = g_Whh_hi[0]; dl = g_Whh_lo[0]; }
    else if (m == 1) { x = W_hh_rest[r];       dh = g_Whh_hi[1]; dl = g_Whh_lo[1]; }
    else if (m == 2) { x = W_hh_rest[MS + r];  dh = g_Whh_hi[2]; dl = g_Whh_lo[2]; }
    else if (m == 3) { x = W_ih_rest[r];       dh = g_Wih_hi[0]; dl = g_Wih_lo[0]; }
    else             { x = W_ih_rest[MS + r];  dh = g_Wih_hi[1]; dl = g_Wih_lo[1]; }
    __nv_bfloat16 hi = __float2bfloat16(x);
    dh[r] = hi;
    dl[r] = __float2bfloat16(x - __bfloat162float(hi));
}

__global__ void zero_state_kernel() {
    int idx = blockIdx.x * 256 + threadIdx.x;
    g_h_f32[idx] = 0.f;
    g_c_f32[idx] = 0.f;
    g_h_hi[idx] = __float2bfloat16(0.f);
    g_h_lo[idx] = __float2bfloat16(0.f);
}

// ---------------- mma.sync step GEMM ----------------
// CTA tile M=128(batch) x N=64(gates), K-chunk 64. grid (64, 2), block 256.
// Per stage: A_hi 16KB, A_lo 16KB, W_hi 8KB, W_lo 8KB = 48KB. 2 stages.
#define ST_A_HI 0
#define ST_A_LO 16384
#define ST_W_HI 32768
#define ST_W_LO 40960
#define STAGE_B 49152
#define DYN_SMEM (2 * STAGE_B + 1024)

__global__ void __launch_bounds__(256) lstm_gemm_kernel(
    int layer, int in_sel, int t,
    const float* __restrict__ bias,
    const float* __restrict__ WihV,     // [4096,32] fp32, layer 0 only
    const int* __restrict__ tokens)     // [B,T], layer 0 only
{
    extern __shared__ char smem_raw[];
    const uint32_t sm0 = (smem_u32_of(smem_raw) + 1023u) & ~1023u;  // 1KB align
    const int tid = threadIdx.x;
    const int w = tid >> 5, lane = tid & 31;
    const int g0 = blockIdx.x * 64;
    const int b0 = blockIdx.y * 128;
    const int mrow = (w & 3) * 32;      // warp M offset (4 warps over 128)
    const int ncol = (w >> 2) * 32;     // warp N offset (2 warps over 64)

    // phase tables: [phase][hi/lo]
    const __nv_bfloat16* Ap[2][2];
    const __nv_bfloat16* Wp[2][2];
    int nph = 0;
    if (layer > 0) {
        const size_t hoff = (size_t)t * Bn * Hn;
        Ap[0][0] = g_hsA_hi[in_sel] + hoff;  Ap[0][1] = g_hsA_lo[in_sel] + hoff;
        Wp[0][0] = g_Wih_hi[layer - 1];      Wp[0][1] = g_Wih_lo[layer - 1];
        nph = 1;
    }
    Ap[nph][0] = g_h_hi;            Ap[nph][1] = g_h_lo;
    Wp[nph][0] = g_Whh_hi[layer];   Wp[nph][1] = g_Whh_lo[layer];
    nph++;
    const int nchunk = nph * 16;

#define ISSUE_LOAD(c_, s_) do {                                                   \
        const int ph_ = (c_) >> 4;                                                \
        const int k0_ = ((c_) & 15) * 64;                                         \
        const uint32_t sb_ = sm0 + (uint32_t)(s_) * STAGE_B;                      \
        _Pragma("unroll")                                                         \
        for (int p_ = 0; p_ < 4; p_++) {                                          \
            int idx_ = p_ * 256 + tid;                                            \
            int row_ = idx_ >> 3, grp_ = idx_ & 7;                                \
            uint32_t so_ = SWZ128((uint32_t)(row_ * 128 + grp_ * 16));            \
            const __nv_bfloat16* a1_ = Ap[ph_][0] + (size_t)(b0 + row_) * Hn + k0_ + grp_ * 8; \
            const __nv_bfloat16* a2_ = Ap[ph_][1] + (size_t)(b0 + row_) * Hn + k0_ + grp_ * 8; \
            asm volatile("cp.async.cg.shared.global [%0], [%1], 16;"              \
                         :: "r"(sb_ + ST_A_HI + so_), "l"(a1_));                  \
            asm volatile("cp.async.cg.shared.global [%0], [%1], 16;"              \
                         :: "r"(sb_ + ST_A_LO + so_), "l"(a2_));                  \
            if (p_ < 2) {                                                         \
                const __nv_bfloat16* w1_ = Wp[ph_][0] + (size_t)(g0 + row_) * Hn + k0_ + grp_ * 8; \
                const __nv_bfloat16* w2_ = Wp[ph_][1] + (size_t)(g0 + row_) * Hn + k0_ + grp_ * 8; \
                asm volatile("cp.async.cg.shared.global [%0], [%1], 16;"          \
                             :: "r"(sb_ + ST_W_HI + so_), "l"(w1_));              \
                asm volatile("cp.async.cg.shared.global [%0], [%1], 16;"          \
                             :: "r"(sb_ + ST_W_LO + so_), "l"(w2_));              \
            }                                                                     \
        }                                                                         \
        asm volatile("cp.async.commit_group;" ::: "memory");                      \
    } while (0)

    float acc[2][4][4];
#pragma unroll
    for (int i = 0; i < 2; i++)
#pragma unroll
        for (int j = 0; j < 4; j++)
#pragma unroll
            for (int k = 0; k < 4; k++) acc[i][j][k] = 0.f;

    ISSUE_LOAD(0, 0);
    ISSUE_LOAD(1, 1);

    // ldmatrix per-lane addressing (canonical x4 quad orderings)
    const int quad = lane >> 3, rin = lane & 7;
    const int a_ro = rin + (quad & 1) * 8;      // A: quads {m0-7,k0},{m8-15,k0},{m0-7,k8},{m8-15,k8}
    const int a_co = (quad >> 1) * 16;
    const int b_ro = rin + (quad >> 1) * 8;     // B: quads {n0-7,k0},{n0-7,k8},{n8-15,k0},{n8-15,k8}
    const int b_co = (quad & 1) * 16;

    for (int c = 0; c < nchunk; c++) {
        const int s = c & 1;
        if (c + 1 < nchunk)
            asm volatile("cp.async.wait_group 1;" ::: "memory");
        else
            asm volatile("cp.async.wait_group 0;" ::: "memory");
        __syncthreads();

        const uint32_t sb = sm0 + (uint32_t)s * STAGE_B;
#pragma unroll
        for (int kk = 0; kk < 4; kk++) {
            uint32_t ahi[2][4], alo[2][4], whi[2][4], wlo[2][4];
#pragma unroll
            for (int mf = 0; mf < 2; mf++) {
                uint32_t off = SWZ128((uint32_t)((mrow + mf * 16 + a_ro) * 128 + kk * 32 + a_co));
                LDSM4(ahi[mf], sb + ST_A_HI + off);
                LDSM4(alo[mf], sb + ST_A_LO + off);
            }
#pragma unroll
            for (int nf2 = 0; nf2 < 2; nf2++) {
                uint32_t off = SWZ128((uint32_t)((ncol + nf2 * 16 + b_ro) * 128 + kk * 32 + b_co));
                LDSM4(whi[nf2], sb + ST_W_HI + off);
                LDSM4(wlo[nf2], sb + ST_W_LO + off);
            }
#pragma unroll
            for (int mf = 0; mf < 2; mf++)
#pragma unroll
                for (int nf = 0; nf < 4; nf++) {
                    int n2 = nf >> 1, su = (nf & 1) * 2;
                    MMA16816(acc[mf][nf], ahi[mf], whi[n2][su], whi[n2][su + 1]);
                    MMA16816(acc[mf][nf], ahi[mf], wlo[n2][su], wlo[n2][su + 1]);
                    MMA16816(acc[mf][nf], alo[mf], whi[n2][su], whi[n2][su + 1]);
                }
        }
        __syncthreads();
        if (c + 2 < nchunk) ISSUE_LOAD(c + 2, s);
    }
#undef ISSUE_LOAD

    // epilogue: bias (+ one-hot col for layer 0), store gates from C fragments.
    // C frag: c0,c1 -> row=gid, cols 2*tig,2*tig+1 ; c2,c3 -> row=gid+8.
    const int gid = lane >> 2, tig = lane & 3;
#pragma unroll
    for (int mf = 0; mf < 2; mf++) {
        int r0 = b0 + mrow + mf * 16 + gid;
        int r1 = r0 + 8;
        int tok0 = 0, tok1 = 0;
        if (tokens != nullptr) {
            tok0 = tokens[r0 * Tn + t];
            tok1 = tokens[r1 * Tn + t];
        }
#pragma unroll
        for (int nf = 0; nf < 4; nf++) {
            int g = g0 + ncol + nf * 8 + tig * 2;
            float bx = bias[g], by = bias[g + 1];
            float x0 = acc[mf][nf][0] + bx, y0 = acc[mf][nf][1] + by;
            float x1 = acc[mf][nf][2] + bx, y1 = acc[mf][nf][3] + by;
            if (WihV != nullptr) {
                x0 += WihV[(size_t)g * Vn + tok0];
                y0 += WihV[(size_t)(g + 1) * Vn + tok0];
                x1 += WihV[(size_t)g * Vn + tok1];
                y1 += WihV[(size_t)(g + 1) * Vn + tok1];
            }
            *reinterpret_cast<float2*>(&g_gates[(size_t)r0 * G4 + g]) = make_float2(x0, y0);
            *reinterpret_cast<float2*>(&g_gates[(size_t)r1 * G4 + g]) = make_float2(x1, y1);
        }
    }
}

// ---------------- pointwise LSTM update ----------------
__global__ void __launch_bounds__(256) update_kernel(
    const int* __restrict__ lengths, int t, int out_sel, int write_f32,
    float* __restrict__ out_h, float* __restrict__ out_c)
{
    int idx = blockIdx.x * 256 + threadIdx.x;  // b*H + j
    int bb = idx >> 10;
    int j = idx & 1023;
    const float* gr = &g_gates[(size_t)bb * G4];
    float gi = gr[j];
    float gf = gr[Hn + j];
    float gg = gr[2 * Hn + j];
    float go = gr[3 * Hn + j];
    float ig = 1.f / (1.f + expf(-gi));
    float fg = 1.f / (1.f + expf(-gf));
    float gt = tanhf(gg);
    float og = 1.f / (1.f + expf(-go));
    float h = g_h_f32[idx];
    float c = g_c_f32[idx];
    if (t < lengths[bb]) {
        c = fg * c + ig * gt;
        h = og * tanhf(c);
        g_h_f32[idx] = h;
        g_c_f32[idx] = c;
    }
    __nv_bfloat16 hi = __float2bfloat16(h);
    __nv_bfloat16 lo = __float2bfloat16(h - __bfloat162float(hi));
    g_h_hi[idx] = hi;
    g_h_lo[idx] = lo;
    size_t hsix = (size_t)t * Bn * Hn + idx;
    if (out_sel >= 0) {
        g_hsA_hi[out_sel][hsix] = hi;
        g_hsA_lo[out_sel][hsix] = lo;
    }
    if (write_f32) g_hs_f32[hsix] = h;
    if (out_h != nullptr) { out_h[idx] = h; out_c[idx] = c; }
}

// ---------------- output head ----------------
__global__ void __launch_bounds__(256) head_kernel(
    const float* __restrict__ W_out, const float* __restrict__ b_out,
    const int* __restrict__ lengths, float* __restrict__ out)
{
    __shared__ float row[Hn];
    int r = blockIdx.x;          // r = t*B + b
    int t = r >> 8;
    int b = r & 255;
    int tid = threadIdx.x;
    int lane = tid & 31, w = tid >> 5;
    float* outp = &out[((size_t)b * Tn + t) * Vn];
    if (t >= lengths[b]) {
        if (tid < Vn) outp[tid] = 0.f;
        return;
    }
    const float* hsrow = &g_hs_f32[(size_t)r * Hn];
    *reinterpret_cast<float4*>(&row[tid * 4]) =
        *reinterpret_cast<const float4*>(&hsrow[tid * 4]);
    __syncthreads();
#pragma unroll
    for (int jv = 0; jv < 4; jv++) {
        int v = w * 4 + jv;
        const float* wr = &W_out[(size_t)v * Hn];
        float s = 0.f;
#pragma unroll 8
        for (int k = lane; k < Hn; k += 32) s += row[k] * wr[k];
#pragma unroll
        for (int off = 16; off; off >>= 1) s += __shfl_xor_sync(0xffffffffu, s, off);
        if (lane == 0) outp[v] = s + b_out[v];
    }
}

// ---------------- launch ----------------
extern "C" void kernel_launch(void* const* d_in, const int* in_sizes, int n_in,
                              void* d_out, int out_size) {
    const int*   tokens    = (const int*)d_in[0];
    const int*   lengths   = (const int*)d_in[1];
    const float* W_ih0     = (const float*)d_in[2];
    const float* W_hh0     = (const float*)d_in[3];
    const float* b0        = (const float*)d_in[4];
    const float* W_ih_rest = (const float*)d_in[5];
    const float* W_hh_rest = (const float*)d_in[6];
    const float* b_rest    = (const float*)d_in[7];
    const float* W_out     = (const float*)d_in[8];
    const float* b_out     = (const float*)d_in[9];
    float* out = (float*)d_out;

    cudaFuncSetAttribute(lstm_gemm_kernel,
                         cudaFuncAttributeMaxDynamicSharedMemorySize, DYN_SMEM);

    float* out_h_base = out + (size_t)Bn * Tn * Vn;
    float* out_c_base = out_h_base + (size_t)3 * Bn * Hn;

    {
        size_t tot = (size_t)5 * G4 * Hn;
        prep_weights_kernel<<<(unsigned)((tot + 255) / 256), 256>>>(W_hh0, W_ih_rest, W_hh_rest);
    }

    dim3 ggrid(64, 2);
    for (int layer = 0; layer < 3; layer++) {
        const float* bias = (layer == 0) ? b0 : b_rest + (size_t)(layer - 1) * G4;
        const float* WihV = (layer == 0) ? W_ih0 : nullptr;
        const int*   toks = (layer == 0) ? tokens : nullptr;
        int in_sel  = (layer == 2) ? 1 : 0;           // layer1 reads 0; layer2 reads 1
        int out_sel = (layer == 0) ? 0 : (layer == 1) ? 1 : -1;
        int wf32    = (layer == 2) ? 1 : 0;

        zero_state_kernel<<<1024, 256>>>();
        for (int t = 0; t < Tn; t++) {
            lstm_gemm_kernel<<<ggrid, 256, DYN_SMEM>>>(layer, in_sel, t, bias, WihV, toks);
            bool last = (t == Tn - 1);
            update_kernel<<<1024, 256>>>(
                lengths, t, out_sel, wf32,
                last ? out_h_base + (size_t)layer * Bn * Hn : nullptr,
                last ? out_c_base + (size_t)layer * Bn * Hn : nullptr);
        }
    }
    head_kernel<<<Tn * Bn, 256>>>(W_out, b_out, lengths, out);
}